// round 6
// baseline (speedup 1.0000x reference)
#include <cuda_runtime.h>
#include <cuda_fp16.h>

#define BB 8
#define NN 4096
#define EE 8190
#define VV 256
#define HH 128
#define TS 131072          // hash table slots (2^17)
#define TSM (TS - 1)
#define CAP 32             // adjacency capacity per node
#define GG 132             // persistent blocks (single wave)
#define TT 1024            // threads per block
#define NNODE (BB * NN)    // 32768
#define SMEM_BYTES (NNODE * 4 + VV * HH * 2)   // 128KB dis + 64KB emb1h = 192KB

// -------- scratch (device globals; zero-initialized, kept clean by each launch) ------
__device__ unsigned int g_tab[TS];             // dedup hash table (key+1, 0=empty)
__device__ int          g_rowcnt[NNODE];       // out-degree / out-cursor
__device__ int          g_incnt[NNODE];        // in-degree / in-cursor
__device__ int          g_adjo[NNODE * CAP];   // out entries: j | (type_j<<12)
__device__ int          g_adji[NNODE * CAP];   // in entries: i
__device__ __half       g_emb1h[VV * HH];      // emb @ w1^T (fp16)
__device__ float        g_pooled[BB * HH];
__device__ unsigned int g_bar_cnt;
__device__ unsigned int g_bar_gen;

__device__ __forceinline__ void gridbar() {
    __syncthreads();
    if (threadIdx.x == 0) {
        __threadfence();
        unsigned gen = *((volatile unsigned*)&g_bar_gen);
        if (atomicAdd(&g_bar_cnt, 1u) == gridDim.x - 1) {
            *((volatile unsigned*)&g_bar_cnt) = 0u;
            __threadfence();
            *((volatile unsigned*)&g_bar_gen) = gen + 1u;
        } else {
            while (*((volatile unsigned*)&g_bar_gen) == gen) { }
            __threadfence();
        }
    }
    __syncthreads();
}

extern __shared__ char smem_raw[];

__global__ void __launch_bounds__(TT, 1)
gnn_all(const int* __restrict__ type_ids, const int* __restrict__ edges,
        const float* __restrict__ emb, const float* __restrict__ w1,
        const float* __restrict__ b1, const float* __restrict__ w2,
        const float* __restrict__ b2, float* __restrict__ out) {
    float*  s_dis = reinterpret_cast<float*>(smem_raw);              // [NNODE]
    __half* s_e1  = reinterpret_cast<__half*>(smem_raw + NNODE * 4); // [VV*HH]

    const int tid  = threadIdx.x;
    const int gtid = blockIdx.x * TT + tid;
    const int lane = tid & 31;
    const int gw   = gtid >> 5;
    const int nw   = (GG * TT) >> 5;          // 4224 warps

    // ---- P1a: edge dedup (set semantics) + adjacency build at insert time ----
    if (gtid < BB * EE) {
        int b = gtid / EE;
        int2 e = reinterpret_cast<const int2*>(edges)[gtid];
        unsigned key1 = (((unsigned)b << 24) | ((unsigned)e.x << 12) | (unsigned)e.y) + 1u;
        unsigned s = ((key1 * 0x9E3779B1u) >> 15) & TSM;
        while (true) {
            unsigned prev = atomicCAS(&g_tab[s], 0u, key1);
            if (prev == 0u) {
                int ni = b * NN + e.x;
                int nj = b * NN + e.y;
                int oc = atomicAdd(&g_rowcnt[ni], 1);
                if (oc < CAP) g_adjo[ni * CAP + oc] = e.y | (type_ids[nj] << 12);
                int ic = atomicAdd(&g_incnt[nj], 1);
                if (ic < CAP) g_adji[nj * CAP + ic] = e.x;
                break;
            }
            if (prev == key1) break;
            s = (s + 1) & TSM;
        }
    }
    // ---- P1b: emb1 = emb @ w1^T (warp dots, coalesced), store fp16 ----
    for (int o = gw; o < VV * HH; o += nw) {
        int v = o >> 7, c = o & 127;
        const float* er = emb + v * HH;
        const float* wr = w1 + c * HH;
        float p = 0.f;
        #pragma unroll
        for (int q = 0; q < 4; q++) { int k = lane + q * 32; p = fmaf(er[k], wr[k], p); }
        #pragma unroll
        for (int off = 16; off; off >>= 1) p += __shfl_xor_sync(0xffffffffu, p, off);
        if (lane == 0) g_emb1h[o] = __float2half(p);
    }
    gridbar();

    // ---- P2: stage dis (all nodes, fp32) + emb1h into smem ----
    for (int i = tid; i < NNODE / 4; i += TT) {
        int4 rc = reinterpret_cast<const int4*>(g_rowcnt)[i];
        float4 d;
        d.x = rsqrtf(1.0f + (float)rc.x);
        d.y = rsqrtf(1.0f + (float)rc.y);
        d.z = rsqrtf(1.0f + (float)rc.z);
        d.w = rsqrtf(1.0f + (float)rc.w);
        reinterpret_cast<float4*>(s_dis)[i] = d;
    }
    for (int i = tid; i < (VV * HH * 2) / 16; i += TT)
        reinterpret_cast<uint4*>(s_e1)[i] = reinterpret_cast<const uint4*>(g_emb1h)[i];
    __syncthreads();

    // ---- node phase: warp-per-8-nodes; h = relu(di*(di*e1+S)+b1); pool += c*h ----
    if (gw < 4096) {
        const int b = gw >> 9;                 // 512 chunks per batch
        const int bN = b * NN;
        const int base = bN + (gw & 511) * 8;
        float bias[4], acc[4];
        #pragma unroll
        for (int q = 0; q < 4; q++) { bias[q] = b1[lane + 32 * q]; acc[q] = 0.f; }

        int od[2], idg[2], ti[2]; int4 oe[2], ie[2];
        // prime node 0
        {
            int ni = base;
            od[0]  = g_rowcnt[ni]; idg[0] = g_incnt[ni]; ti[0] = type_ids[ni];
            oe[0]  = *reinterpret_cast<const int4*>(&g_adjo[ni * CAP]);
            ie[0]  = *reinterpret_cast<const int4*>(&g_adji[ni * CAP]);
        }
        #pragma unroll
        for (int n = 0; n < 8; n++) {
            int cur = n & 1, nxt = cur ^ 1;
            if (n < 7) {
                int ni = base + n + 1;
                od[nxt]  = g_rowcnt[ni]; idg[nxt] = g_incnt[ni]; ti[nxt] = type_ids[ni];
                oe[nxt]  = *reinterpret_cast<const int4*>(&g_adjo[ni * CAP]);
                ie[nxt]  = *reinterpret_cast<const int4*>(&g_adji[ni * CAP]);
            }
            float di = s_dis[base + n];
            float sacc[4];
            #pragma unroll
            for (int q = 0; q < 4; q++)
                sacc[q] = di * __half2float(s_e1[ti[cur] * HH + lane + 32 * q]);
            int o_ = od[cur];
            if (o_ > 0) { int v = oe[cur].x; float dj = s_dis[bN + (v & 4095)]; int t = v >> 12;
                #pragma unroll
                for (int q = 0; q < 4; q++) sacc[q] = fmaf(dj, __half2float(s_e1[t * HH + lane + 32 * q]), sacc[q]); }
            if (o_ > 1) { int v = oe[cur].y; float dj = s_dis[bN + (v & 4095)]; int t = v >> 12;
                #pragma unroll
                for (int q = 0; q < 4; q++) sacc[q] = fmaf(dj, __half2float(s_e1[t * HH + lane + 32 * q]), sacc[q]); }
            if (o_ > 2) { int v = oe[cur].z; float dj = s_dis[bN + (v & 4095)]; int t = v >> 12;
                #pragma unroll
                for (int q = 0; q < 4; q++) sacc[q] = fmaf(dj, __half2float(s_e1[t * HH + lane + 32 * q]), sacc[q]); }
            if (o_ > 3) { int v = oe[cur].w; float dj = s_dis[bN + (v & 4095)]; int t = v >> 12;
                #pragma unroll
                for (int q = 0; q < 4; q++) sacc[q] = fmaf(dj, __half2float(s_e1[t * HH + lane + 32 * q]), sacc[q]); }
            if (o_ > 4) {
                int dmax = min(o_, CAP);
                for (int d = 4; d < dmax; d++) {
                    int v = g_adjo[(base + n) * CAP + d];
                    float dj = s_dis[bN + (v & 4095)]; int t = v >> 12;
                    #pragma unroll
                    for (int q = 0; q < 4; q++) sacc[q] = fmaf(dj, __half2float(s_e1[t * HH + lane + 32 * q]), sacc[q]);
                }
            }
            float ins = 0.f;
            int in_ = idg[cur];
            if (in_ > 0) ins += s_dis[bN + (ie[cur].x & 4095)];
            if (in_ > 1) ins += s_dis[bN + (ie[cur].y & 4095)];
            if (in_ > 2) ins += s_dis[bN + (ie[cur].z & 4095)];
            if (in_ > 3) ins += s_dis[bN + (ie[cur].w & 4095)];
            if (in_ > 4) {
                int dmax = min(in_, CAP);
                for (int d = 4; d < dmax; d++)
                    ins += s_dis[bN + (g_adji[(base + n) * CAP + d] & 4095)];
            }
            float cc = di * (di + ins);
            #pragma unroll
            for (int q = 0; q < 4; q++) {
                float hv = fmaxf(fmaf(di, sacc[q], bias[q]), 0.f);
                acc[q] = fmaf(cc, hv, acc[q]);
            }
        }
        #pragma unroll
        for (int q = 0; q < 4; q++)
            atomicAdd(&g_pooled[b * HH + lane + 32 * q], acc[q]);
    }
    gridbar();

    // ---- P3: blocks 0..7: GEMV + normalize (+ zero pooled); blocks 8+: clear scratch --
    if (blockIdx.x < BB) {
        const int b = blockIdx.x;
        __shared__ float xs[HH];
        __shared__ float zsh[HH];
        __shared__ float nsum;
        if (tid < HH) {
            xs[tid] = g_pooled[b * HH + tid] * (1.0f / NN);
            g_pooled[b * HH + tid] = 0.f;          // deferred clean for next launch
        }
        if (tid == 0) nsum = 0.f;
        __syncthreads();
        const int w = tid >> 5;                    // 32 warps -> 4 rows each
        float sqp = 0.f;
        for (int r = w * 4; r < w * 4 + 4; r++) {
            const float* wr = w2 + r * HH;
            float p = 0.f;
            #pragma unroll
            for (int q = 0; q < 4; q++) { int k = lane + q * 32; p = fmaf(wr[k], xs[k], p); }
            #pragma unroll
            for (int off = 16; off; off >>= 1) p += __shfl_xor_sync(0xffffffffu, p, off);
            if (lane == 0) {
                float z = p + b2[r];
                zsh[r] = z;
                sqp = fmaf(z, z, sqp);
            }
        }
        if (lane == 0) atomicAdd(&nsum, sqp);
        __syncthreads();
        if (tid < HH) {
            float nrm = fmaxf(sqrtf(nsum), 1e-12f);
            out[b * HH + tid] = zsh[tid] / nrm;
        }
    } else {
        // clear table + degree counters for the next launch (768KB over 124 blocks)
        int cid = (blockIdx.x - BB) * TT + tid;
        int csz = (GG - BB) * TT;
        uint4 z4 = make_uint4(0u, 0u, 0u, 0u);
        for (int i = cid; i < TS / 4; i += csz)
            reinterpret_cast<uint4*>(g_tab)[i] = z4;
        for (int i = cid; i < NNODE / 4; i += csz) {
            reinterpret_cast<uint4*>(g_rowcnt)[i] = z4;
            reinterpret_cast<uint4*>(g_incnt)[i] = z4;
        }
    }
}

extern "C" void kernel_launch(void* const* d_in, const int* in_sizes, int n_in,
                              void* d_out, int out_size) {
    const int*   type_ids = (const int*)d_in[0];
    const int*   edges    = (const int*)d_in[1];
    const float* emb      = (const float*)d_in[2];
    const float* w1       = (const float*)d_in[3];
    const float* b1       = (const float*)d_in[4];
    const float* w2       = (const float*)d_in[5];
    const float* b2       = (const float*)d_in[6];
    float* out = (float*)d_out;

    static int smem_set = 0;
    if (!smem_set) {
        cudaFuncSetAttribute(gnn_all, cudaFuncAttributeMaxDynamicSharedMemorySize, SMEM_BYTES);
        smem_set = 1;
    }
    gnn_all<<<GG, TT, SMEM_BYTES>>>(type_ids, edges, emb, w1, b1, w2, b2, out);
}